// round 8
// baseline (speedup 1.0000x reference)
#include <cuda_runtime.h>
#include <cuda_bf16.h>
#include <stdint.h>
#include <math.h>

#define BB 4
#define CC 32
#define HWPIX 65536
#define SS 8
#define NN 262144
#define QQ 256
#define NEGS 256
#define NCHUNK 256
#define CHUNK 1024
#define TBLSTRIDE 32768
#define FPSCALE 16777216.0f
#define INV_FPSCALE (1.0/16777216.0)
#define TINYF 1.17549435e-38f
#define NEG_INF (__int_as_float(0xFF800000))
#define POS_INF (__int_as_float(0x7F800000))

// ---------------- device scratch ----------------
__device__ uint8_t g_cls[NN];
__device__ int g_chunkCntV[SS*NCHUNK];
__device__ int g_chunkCntH[SS*NCHUNK];
__device__ int g_offV[SS*NCHUNK];
__device__ int g_offH[SS*NCHUNK];
__device__ int g_countV[SS];
__device__ int g_countH[SS];
__device__ unsigned long long g_protoLL[SS*CC*3];
__device__ float g_B[(size_t)NN*CC];   // l2norm(mu)*w
__device__ float g_D[(size_t)NN*CC];   // sigma*w
__device__ int g_tblV[SS*TBLSTRIDE];
__device__ int g_tblH[SS*TBLSTRIDE];
__device__ float g_logits7[SS*7];
__device__ float g_posB[SS*CC];
__device__ float g_posD[SS*CC];
__device__ int g_apix[SS*QQ];
__device__ int g_npix[SS*QQ*NEGS];
__device__ float g_ce[SS*QQ];

// ---------------- JAX threefry2x32 (exact) ----------------
__device__ __forceinline__ uint2 tf2(uint32_t k0, uint32_t k1, uint32_t c0, uint32_t c1){
  uint32_t ks2 = k0 ^ k1 ^ 0x1BD11BDAu;
  uint32_t x0 = c0 + k0;
  uint32_t x1 = c1 + k1;
#define TFR(d) { x0 += x1; x1 = ((x1 << (d)) | (x1 >> (32-(d)))); x1 ^= x0; }
  TFR(13) TFR(15) TFR(26) TFR(6)
  x0 += k1;  x1 += ks2 + 1u;
  TFR(17) TFR(29) TFR(16) TFR(24)
  x0 += ks2; x1 += k0 + 2u;
  TFR(13) TFR(15) TFR(26) TFR(6)
  x0 += k0;  x1 += k1 + 3u;
  TFR(17) TFR(29) TFR(16) TFR(24)
  x0 += k1;  x1 += ks2 + 4u;
  TFR(13) TFR(15) TFR(26) TFR(6)
  x0 += ks2; x1 += k0 + 5u;
#undef TFR
  return make_uint2(x0, x1);
}
__device__ __forceinline__ float u01f(uint32_t bits){
  return __uint_as_float((bits >> 9) | 0x3F800000u) - 1.0f;
}
__device__ __forceinline__ float wsum32(float v){
  #pragma unroll
  for (int d = 16; d; d >>= 1) v += __shfl_xor_sync(0xFFFFFFFFu, v, d);
  return v;
}

// ---------------- K0: clear proto accumulators ----------------
__global__ void k0_clear(){
  for (int i = threadIdx.x; i < SS*CC*3; i += 256) g_protoLL[i] = 0ull;
}

// ---------------- K1: classify pixels + per-chunk counts ----------------
__global__ void k1_classify(const float* __restrict__ label,
                            const float* __restrict__ mask,
                            const float* __restrict__ prob){
  __shared__ int cV[SS], cH[SS];
  if (threadIdx.x < SS){ cV[threadIdx.x] = 0; cH[threadIdx.x] = 0; }
  __syncthreads();
  int chunk = blockIdx.x;
  for (int k = 0; k < CHUNK/256; k++){
    int n = chunk*CHUNK + k*256 + threadIdx.x;
    int b = n >> 16, hw = n & (HWPIX-1);
    float mk = mask[b*HWPIX + hw];
    int cls = -1;
    #pragma unroll
    for (int s = 0; s < SS; s++){
      float lv = label[((size_t)b*SS + s)*HWPIX + hw];
      if (lv > 0.0f) cls = s;
    }
    uint8_t byte = 0xFF;
    if (mk > 0.0f && cls >= 0){
      float p = prob[((size_t)b*SS + cls)*HWPIX + hw];
      int hard = (p < 0.97f) ? 1 : 0;
      byte = (uint8_t)(cls | (hard << 4));
      atomicAdd(&cV[cls], 1);
      if (hard) atomicAdd(&cH[cls], 1);
    }
    g_cls[n] = byte;
  }
  __syncthreads();
  if (threadIdx.x < SS){
    g_chunkCntV[threadIdx.x*NCHUNK + chunk] = cV[threadIdx.x];
    g_chunkCntH[threadIdx.x*NCHUNK + chunk] = cH[threadIdx.x];
  }
}

// ---------------- K2: transpose -> B/D vectors + fixed-point proto sums ----------------
__global__ void k2_transpose(const float* __restrict__ W,
                             const float* __restrict__ MU,
                             const float* __restrict__ SG){
  __shared__ float sw[32*65], smu[32*65], ssg[32*65];
  __shared__ unsigned long long acc[SS*CC*3];
  __shared__ uint8_t scls[64];
  int t = threadIdx.x;
  for (int i = t; i < SS*CC*3; i += 256) acc[i] = 0ull;
  int n0 = blockIdx.x * 64;
  int b = n0 >> 16, hw0 = n0 & (HWPIX-1);
  size_t base = (size_t)b*CC*HWPIX + hw0;
  for (int idx = t; idx < 2048; idx += 256){
    int c = idx >> 6, p = idx & 63;
    size_t gidx = base + (size_t)c*HWPIX + p;
    sw[c*65+p]  = W[gidx];
    smu[c*65+p] = MU[gidx];
    ssg[c*65+p] = SG[gidx];
  }
  if (t < 64) scls[t] = g_cls[n0 + t];
  __syncthreads();
  int c = t & 31, p0 = t >> 5;
  for (int p = p0; p < 64; p += 8){
    float w  = sw[c*65+p];
    float mu = smu[c*65+p];
    float sg = ssg[c*65+p];
    float nrm = sqrtf(wsum32(mu*mu));
    float mun = mu / fmaxf(nrm, 1e-12f);
    size_t o = (size_t)(n0 + p)*CC + c;
    g_B[o] = mun * w;
    g_D[o] = sg * w;
    uint8_t cb = scls[p];
    if (cb != 0xFF){
      int s = cb & 7;
      float isw = w / sg;
      float iw  = 1.0f / w;
      long long a0 = llrintf(isw * FPSCALE);
      long long a1 = llrintf((isw * mu) * FPSCALE);
      long long a2 = llrintf(iw * FPSCALE);
      atomicAdd(&acc[(s*CC + c)*3 + 0], (unsigned long long)a0);
      atomicAdd(&acc[(s*CC + c)*3 + 1], (unsigned long long)a1);
      atomicAdd(&acc[(s*CC + c)*3 + 2], (unsigned long long)a2);
    }
  }
  __syncthreads();
  for (int i = t; i < SS*CC*3; i += 256)
    if (acc[i]) atomicAdd(&g_protoLL[i], acc[i]);
}

// ---------------- K3: per-class chunk offset scan ----------------
__global__ void k3_scan(){
  int s = threadIdx.x;
  if (s < SS){
    int run = 0;
    for (int ch = 0; ch < NCHUNK; ch++){ g_offV[s*NCHUNK+ch] = run; run += g_chunkCntV[s*NCHUNK+ch]; }
    g_countV[s] = run;
    run = 0;
    for (int ch = 0; ch < NCHUNK; ch++){ g_offH[s*NCHUNK+ch] = run; run += g_chunkCntH[s*NCHUNK+ch]; }
    g_countH[s] = run;
  }
}

// ---------------- K3b: stable rank tables via warp ballot ----------------
__global__ void k3b_rank(){
  int chunk = blockIdx.x, lane = threadIdx.x;
  int cntV[8], cntH[8], baseV[8], baseH[8];
  #pragma unroll
  for (int s=0;s<8;s++){
    cntV[s]=0; cntH[s]=0;
    baseV[s]=g_offV[s*NCHUNK+chunk]; baseH[s]=g_offH[s*NCHUNK+chunk];
  }
  unsigned lt = (1u<<lane)-1u;
  for (int g=0; g<32; g++){
    int n = chunk*CHUNK + g*32 + lane;
    uint8_t b = g_cls[n];
    bool val = (b != 0xFF);
    int myc = b & 7;
    bool hrd = val && (b & 16);
    #pragma unroll
    for (int s=0;s<8;s++){
      unsigned mV = __ballot_sync(0xFFFFFFFFu, val && myc==s);
      unsigned mH = __ballot_sync(0xFFFFFFFFu, hrd && myc==s);
      if (val && myc==s){
        g_tblV[s*TBLSTRIDE + baseV[s] + cntV[s] + __popc(mV&lt)] = n;
        if (hrd) g_tblH[s*TBLSTRIDE + baseH[s] + cntH[s] + __popc(mH&lt)] = n;
      }
      cntV[s] += __popc(mV); cntH[s] += __popc(mH);
    }
  }
}

// ---------------- K4: prototypes + class-similarity logits ----------------
__global__ void k4_proto(){
  __shared__ float sPB[8][32], sPD[8][32];
  int t = threadIdx.x, s = t>>5, c = t&31;
  long long a0 = (long long)g_protoLL[(s*CC+c)*3+0];
  long long a1 = (long long)g_protoLL[(s*CC+c)*3+1];
  long long a2 = (long long)g_protoLL[(s*CC+c)*3+2];
  float sA = (float)((double)a0*INV_FPSCALE);
  float sB = (float)((double)a1*INV_FPSCALE);
  float sC = (float)((double)a2*INV_FPSCALE);
  float psig = 1.0f/sA;
  float pmu  = psig*sB;
  float pw   = 1.0f/sC;
  float nrm = sqrtf(wsum32(pmu*pmu));
  float pn = pmu / fmaxf(nrm, 1e-12f);
  float pb = pn*pw, pd = psig*pw;
  sPB[s][c]=pb; sPD[s][c]=pd;
  g_posB[s*CC+c]=pb; g_posD[s*CC+c]=pd;
  __syncthreads();
  for (int jj=0; jj<7; jj++){
    int j = (s+1+jj)&7;
    float d  = sPB[s][c]-sPB[j][c];
    float dn = sPD[s][c]+sPD[j][c];
    float part = d*d/dn + logf(dn);
    float tot = wsum32(part);
    if (c==0){
      float sim = -0.5f*(tot/32.0f);
      g_logits7[s*7+jj] = (g_countV[j]>0) ? sim*2.0f : NEG_INF;  // /TEMP
    }
  }
}

// ---------------- K5: anchor sampling ----------------
__global__ void k5_anchor(){
  int i = blockIdx.x, q = threadIdx.x;
  uint2 keyi = tf2(0u, 42u, 0u, (uint32_t)i);
  uint2 ka   = tf2(keyi.x, keyi.y, 0u, 0u);
  uint2 bu   = tf2(ka.x, ka.y, 0u, (uint32_t)q);
  float u = u01f(bu.x ^ bu.y);
  int hc = g_countH[i];
  int r = (int)(u * (float)hc);
  int rm = hc - 1; if (rm < 0) rm = 0;
  if (r > rm) r = rm;
  g_apix[i*QQ+q] = g_tblH[i*TBLSTRIDE + r];
}

// ---------------- K6: categorical (gumbel-equivalent) + negative pixels ----------------
__global__ void k6_neg(){
  __shared__ float w7[7];
  __shared__ int scnt[8], sord[7];
  int iq = blockIdx.x; int i = iq>>8, q = iq&255; int e = threadIdx.x;
  if (e < 8) scnt[e] = g_countV[e];
  if (e == 0){
    float L[7]; float Lmax = NEG_INF;
    for (int jj=0; jj<7; jj++){ L[jj]=g_logits7[i*7+jj]; if (L[jj]>Lmax) Lmax=L[jj]; }
    for (int jj=0; jj<7; jj++){
      float a = -(L[jj]-Lmax);
      if (!(a < 80.0f)) a = 80.0f;
      w7[jj] = expf(a);
      sord[jj] = (i+1+jj)&7;
    }
  }
  __syncthreads();
  uint2 keyi = tf2(0u, 42u, 0u, (uint32_t)i);
  uint2 kb = tf2(keyi.x, keyi.y, 0u, 1u);
  uint2 kc = tf2(keyi.x, keyi.y, 0u, 2u);
  uint32_t base = ((uint32_t)q*256u + (uint32_t)e)*7u;
  int best = 0; float bs = POS_INF;
  #pragma unroll
  for (int jj=0; jj<7; jj++){
    uint2 bb = tf2(kb.x, kb.y, 0u, base + (uint32_t)jj);
    float u = u01f(bb.x ^ bb.y);
    float f = fmaxf(u + TINYF, TINYF);
    float score = (-logf(f)) * w7[jj];   // argmin == argmax(gumbel+logit)
    if (score < bs){ bs = score; best = jj; }
  }
  int nc  = sord[best];
  int cnt = scnt[nc];
  uint2 b3 = tf2(kc.x, kc.y, 0u, (uint32_t)(q*256 + e));
  float u3 = u01f(b3.x ^ b3.y);
  int r = (int)(u3 * (float)cnt);
  int rm = cnt - 1; if (rm < 0) rm = 0;
  if (r > rm) r = rm;
  g_npix[iq*NEGS + e] = g_tblV[nc*TBLSTRIDE + r];
}

// ---------------- K7: per-(class,query) MLS logits + logsumexp ----------------
__global__ void k7_mls(){
  __shared__ float sA[32], sD[32], sl[257], red[256];
  __shared__ int snp[256];
  int t = threadIdx.x; int iq = blockIdx.x; int i = iq>>8;
  if (t < 32){
    int ap = g_apix[iq];
    sA[t] = g_B[(size_t)ap*CC + t];
    sD[t] = g_D[(size_t)ap*CC + t];
  }
  snp[t] = g_npix[iq*NEGS + t];
  __syncthreads();
  int w = t>>5, c = t&31;
  float A = sA[c], Da = sD[c];
  for (int j = w; j < 257; j += 8){
    float Bv, Dv;
    if (j == 0){ Bv = g_posB[i*CC+c]; Dv = g_posD[i*CC+c]; }
    else { int p = snp[j-1]; Bv = g_B[(size_t)p*CC+c]; Dv = g_D[(size_t)p*CC+c]; }
    float dn = Da + Dv;
    float d  = A - Bv;
    float part = __fdividef(d*d, dn) + __logf(dn);
    float tot = wsum32(part);
    if (c == 0) sl[j] = -tot*(1.0f/32.0f);   // -0.5*mean/TEMP
  }
  __syncthreads();
  float v = sl[t]; if (t == 0) v = fmaxf(v, sl[256]);
  red[t] = v; __syncthreads();
  for (int o = 128; o; o >>= 1){ if (t < o) red[t] = fmaxf(red[t], red[t+o]); __syncthreads(); }
  float m = red[0]; __syncthreads();
  float ev = expf(sl[t]-m); if (t == 0) ev += expf(sl[256]-m);
  red[t] = ev; __syncthreads();
  for (int o = 128; o; o >>= 1){ if (t < o) red[t] += red[t+o]; __syncthreads(); }
  if (t == 0) g_ce[iq] = (logf(red[0]) + m) - sl[0];
}

// ---------------- K8: deterministic final reduction ----------------
__global__ void k8_final(float* out){
  if (threadIdx.x == 0){
    int vn = 0; float tot = 0.0f;
    for (int i = 0; i < SS; i++) if (g_countV[i] > 0) vn++;
    for (int i = 0; i < SS; i++){
      if (g_countV[i] > 0 && g_countH[i] > 0){
        float s = 0.0f;
        for (int q = 0; q < QQ; q++) s += g_ce[i*QQ+q];
        tot += s / (float)QQ;
      }
    }
    out[0] = tot / (float)(vn > 0 ? vn : 1);
  }
}

extern "C" void kernel_launch(void* const* d_in, const int* in_sizes, int n_in,
                              void* d_out, int out_size){
  const float* W  = (const float*)d_in[0];
  const float* MU = (const float*)d_in[1];
  const float* SG = (const float*)d_in[2];
  const float* LB = (const float*)d_in[3];
  const float* MK = (const float*)d_in[4];
  const float* PR = (const float*)d_in[5];
  float* out = (float*)d_out;
  k0_clear<<<1,256>>>();
  k1_classify<<<NCHUNK,256>>>(LB, MK, PR);
  k2_transpose<<<NN/64,256>>>(W, MU, SG);
  k3_scan<<<1,32>>>();
  k3b_rank<<<NCHUNK,32>>>();
  k4_proto<<<1,256>>>();
  k5_anchor<<<SS,QQ>>>();
  k6_neg<<<SS*QQ,NEGS>>>();
  k7_mls<<<SS*QQ,256>>>();
  k8_final<<<1,32>>>(out);
}

// round 10
// speedup vs baseline: 1.3724x; 1.3724x over previous
#include <cuda_runtime.h>
#include <cuda_bf16.h>
#include <stdint.h>
#include <math.h>

#define BB 4
#define CC 32
#define HWPIX 65536
#define SS 8
#define NN 262144
#define QQ 256
#define NEGS 256
#define NCHUNK 256
#define CHUNK 1024
#define TBLSTRIDE 32768
#define FPSCALE 16777216.0f
#define INV_FPSCALE (1.0/16777216.0)
#define TINYF 1.17549435e-38f
#define NEG_INF (__int_as_float(0xFF800000))
#define POS_INF (__int_as_float(0x7F800000))

// ---------------- device scratch ----------------
__device__ uint8_t g_cls[NN];
__device__ int g_chunkCntV[SS*NCHUNK];
__device__ int g_chunkCntH[SS*NCHUNK];
__device__ int g_offV[SS*NCHUNK];
__device__ int g_offH[SS*NCHUNK];
__device__ int g_countV[SS];
__device__ int g_countH[SS];
__device__ unsigned long long g_protoLL[SS*CC*3];
__device__ float g_B[(size_t)NN*CC];   // l2norm(mu)*w
__device__ float g_D[(size_t)NN*CC];   // sigma*w
__device__ int g_tblV[SS*TBLSTRIDE];
__device__ int g_tblH[SS*TBLSTRIDE];
__device__ float g_w7[SS*7];
__device__ float g_posB[SS*CC];
__device__ float g_posD[SS*CC];
__device__ float g_ce[SS*QQ];

// ---------------- JAX threefry2x32 (exact) ----------------
__device__ __forceinline__ uint2 tf2(uint32_t k0, uint32_t k1, uint32_t c0, uint32_t c1){
  uint32_t ks2 = k0 ^ k1 ^ 0x1BD11BDAu;
  uint32_t x0 = c0 + k0;
  uint32_t x1 = c1 + k1;
#define TFR(d) { x0 += x1; x1 = ((x1 << (d)) | (x1 >> (32-(d)))); x1 ^= x0; }
  TFR(13) TFR(15) TFR(26) TFR(6)
  x0 += k1;  x1 += ks2 + 1u;
  TFR(17) TFR(29) TFR(16) TFR(24)
  x0 += ks2; x1 += k0 + 2u;
  TFR(13) TFR(15) TFR(26) TFR(6)
  x0 += k0;  x1 += k1 + 3u;
  TFR(17) TFR(29) TFR(16) TFR(24)
  x0 += k1;  x1 += ks2 + 4u;
  TFR(13) TFR(15) TFR(26) TFR(6)
  x0 += ks2; x1 += k0 + 5u;
#undef TFR
  return make_uint2(x0, x1);
}
__device__ __forceinline__ float u01f(uint32_t bits){
  return __uint_as_float((bits >> 9) | 0x3F800000u) - 1.0f;
}
__device__ __forceinline__ float wsum32(float v){
  #pragma unroll
  for (int d = 16; d; d >>= 1) v += __shfl_xor_sync(0xFFFFFFFFu, v, d);
  return v;
}

// ---------------- K1: classify pixels + per-chunk counts (+clear protos) ----------------
__global__ void k1_classify(const float* __restrict__ label,
                            const float* __restrict__ mask,
                            const float* __restrict__ prob){
  __shared__ int cV[SS], cH[SS];
  if (blockIdx.x == 0){
    for (int i = threadIdx.x; i < SS*CC*3; i += 256) g_protoLL[i] = 0ull;
  }
  if (threadIdx.x < SS){ cV[threadIdx.x] = 0; cH[threadIdx.x] = 0; }
  __syncthreads();
  int chunk = blockIdx.x;
  for (int k = 0; k < CHUNK/256; k++){
    int n = chunk*CHUNK + k*256 + threadIdx.x;
    int b = n >> 16, hw = n & (HWPIX-1);
    float mk = mask[b*HWPIX + hw];
    int cls = -1;
    #pragma unroll
    for (int s = 0; s < SS; s++){
      float lv = label[((size_t)b*SS + s)*HWPIX + hw];
      if (lv > 0.0f) cls = s;
    }
    uint8_t byte = 0xFF;
    if (mk > 0.0f && cls >= 0){
      float p = prob[((size_t)b*SS + cls)*HWPIX + hw];
      int hard = (p < 0.97f) ? 1 : 0;
      byte = (uint8_t)(cls | (hard << 4));
      atomicAdd(&cV[cls], 1);
      if (hard) atomicAdd(&cH[cls], 1);
    }
    g_cls[n] = byte;
  }
  __syncthreads();
  if (threadIdx.x < SS){
    g_chunkCntV[threadIdx.x*NCHUNK + chunk] = cV[threadIdx.x];
    g_chunkCntH[threadIdx.x*NCHUNK + chunk] = cH[threadIdx.x];
  }
}

// ---------------- K2: transpose -> B/D vectors + fixed-point proto sums ----------------
__global__ void k2_transpose(const float* __restrict__ W,
                             const float* __restrict__ MU,
                             const float* __restrict__ SG){
  __shared__ float sw[32*65], smu[32*65], ssg[32*65];
  __shared__ unsigned long long acc[SS*CC*3];
  __shared__ uint8_t scls[64];
  int t = threadIdx.x;
  for (int i = t; i < SS*CC*3; i += 256) acc[i] = 0ull;
  int n0 = blockIdx.x * 64;
  int b = n0 >> 16, hw0 = n0 & (HWPIX-1);
  size_t base = (size_t)b*CC*HWPIX + hw0;
  for (int idx = t; idx < 2048; idx += 256){
    int c = idx >> 6, p = idx & 63;
    size_t gidx = base + (size_t)c*HWPIX + p;
    sw[c*65+p]  = W[gidx];
    smu[c*65+p] = MU[gidx];
    ssg[c*65+p] = SG[gidx];
  }
  if (t < 64) scls[t] = g_cls[n0 + t];
  __syncthreads();
  int c = t & 31, p0 = t >> 5;
  for (int p = p0; p < 64; p += 8){
    float w  = sw[c*65+p];
    float mu = smu[c*65+p];
    float sg = ssg[c*65+p];
    float nrm = sqrtf(wsum32(mu*mu));
    float mun = mu / fmaxf(nrm, 1e-12f);
    size_t o = (size_t)(n0 + p)*CC + c;
    g_B[o] = mun * w;
    g_D[o] = sg * w;
    uint8_t cb = scls[p];
    if (cb != 0xFF){
      int s = cb & 7;
      float isw = w / sg;
      float iw  = 1.0f / w;
      long long a0 = llrintf(isw * FPSCALE);
      long long a1 = llrintf((isw * mu) * FPSCALE);
      long long a2 = llrintf(iw * FPSCALE);
      atomicAdd(&acc[(s*CC + c)*3 + 0], (unsigned long long)a0);
      atomicAdd(&acc[(s*CC + c)*3 + 1], (unsigned long long)a1);
      atomicAdd(&acc[(s*CC + c)*3 + 2], (unsigned long long)a2);
    }
  }
  __syncthreads();
  for (int i = t; i < SS*CC*3; i += 256)
    if (acc[i]) atomicAdd(&g_protoLL[i], acc[i]);
}

// ---------------- K3: parallel per-class chunk offset scan (16 warps) ----------------
__global__ void k3_scan(){
  int t = threadIdx.x, w = t>>5, lane = t&31;
  int s = w >> 1; bool H = (w & 1);
  const int* cnt = H ? g_chunkCntH : g_chunkCntV;
  int* off = H ? g_offH : g_offV;
  int carry = 0;
  #pragma unroll
  for (int seg = 0; seg < 8; seg++){
    int v = cnt[s*NCHUNK + seg*32 + lane];
    int x = v;
    #pragma unroll
    for (int d = 1; d < 32; d <<= 1){
      int y = __shfl_up_sync(0xFFFFFFFFu, x, d);
      if (lane >= d) x += y;
    }
    off[s*NCHUNK + seg*32 + lane] = carry + x - v;
    carry += __shfl_sync(0xFFFFFFFFu, x, 31);
  }
  if (lane == 0){
    if (H) g_countH[s] = carry; else g_countV[s] = carry;
  }
}

// ---------------- K3b: stable rank tables via warp ballot ----------------
__global__ void k3b_rank(){
  int chunk = blockIdx.x, lane = threadIdx.x;
  int cntV[8], cntH[8], baseV[8], baseH[8];
  #pragma unroll
  for (int s=0;s<8;s++){
    cntV[s]=0; cntH[s]=0;
    baseV[s]=g_offV[s*NCHUNK+chunk]; baseH[s]=g_offH[s*NCHUNK+chunk];
  }
  unsigned lt = (1u<<lane)-1u;
  for (int g=0; g<32; g++){
    int n = chunk*CHUNK + g*32 + lane;
    uint8_t b = g_cls[n];
    bool val = (b != 0xFF);
    int myc = b & 7;
    bool hrd = val && (b & 16);
    #pragma unroll
    for (int s=0;s<8;s++){
      unsigned mV = __ballot_sync(0xFFFFFFFFu, val && myc==s);
      unsigned mH = __ballot_sync(0xFFFFFFFFu, hrd && myc==s);
      if (val && myc==s){
        g_tblV[s*TBLSTRIDE + baseV[s] + cntV[s] + __popc(mV&lt)] = n;
        if (hrd) g_tblH[s*TBLSTRIDE + baseH[s] + cntH[s] + __popc(mH&lt)] = n;
      }
      cntV[s] += __popc(mV); cntH[s] += __popc(mH);
    }
  }
}

// ---------------- K4: prototypes + categorical weights ----------------
__global__ void k4_proto(){
  __shared__ float sPB[8][32], sPD[8][32];
  int t = threadIdx.x, s = t>>5, c = t&31;
  long long a0 = (long long)g_protoLL[(s*CC+c)*3+0];
  long long a1 = (long long)g_protoLL[(s*CC+c)*3+1];
  long long a2 = (long long)g_protoLL[(s*CC+c)*3+2];
  float sA = (float)((double)a0*INV_FPSCALE);
  float sB = (float)((double)a1*INV_FPSCALE);
  float sC = (float)((double)a2*INV_FPSCALE);
  float psig = 1.0f/sA;
  float pmu  = psig*sB;
  float pw   = 1.0f/sC;
  float nrm = sqrtf(wsum32(pmu*pmu));
  float pn = pmu / fmaxf(nrm, 1e-12f);
  float pb = pn*pw, pd = psig*pw;
  sPB[s][c]=pb; sPD[s][c]=pd;
  g_posB[s*CC+c]=pb; g_posD[s*CC+c]=pd;
  __syncthreads();
  float Lv[7];
  for (int jj=0; jj<7; jj++){
    int j = (s+1+jj)&7;
    float d  = sPB[s][c]-sPB[j][c];
    float dn = sPD[s][c]+sPD[j][c];
    float part = d*d/dn + logf(dn);
    float tot = wsum32(part);
    if (c==0){
      float sim = -0.5f*(tot/32.0f);
      Lv[jj] = (g_countV[j]>0) ? sim*2.0f : NEG_INF;   // /TEMP
    }
  }
  if (c==0){
    float Lmax = NEG_INF;
    #pragma unroll
    for (int jj=0;jj<7;jj++) Lmax = fmaxf(Lmax, Lv[jj]);
    #pragma unroll
    for (int jj=0;jj<7;jj++){
      float a = -(Lv[jj]-Lmax);
      if (!(a < 80.0f)) a = 80.0f;
      g_w7[s*7+jj] = expf(a);
    }
  }
}

// ---------------- K567: anchor + negatives + MLS logits + logsumexp (fused) ----------------
__global__ void k567_mls(){
  __shared__ float sA[32], sD[32], sl[257], red[256], w7s[7];
  __shared__ int snp[256], scnt8[8], sapix;
  int iq = blockIdx.x; int i = iq>>8, q = iq&255; int t = threadIdx.x;
  if (t < 8) scnt8[t] = g_countV[t];
  if (t < 7) w7s[t] = g_w7[i*7+t];
  if (t == 0){
    uint2 keyi = tf2(0u, 42u, 0u, (uint32_t)i);
    uint2 ka   = tf2(keyi.x, keyi.y, 0u, 0u);
    uint2 bu   = tf2(ka.x, ka.y, 0u, (uint32_t)q);
    float u = u01f(bu.x ^ bu.y);
    int hc = g_countH[i];
    int r = (int)(u * (float)hc);
    int rm = hc - 1; if (rm < 0) rm = 0;
    if (r > rm) r = rm;
    sapix = g_tblH[i*TBLSTRIDE + r];
  }
  __syncthreads();
  if (t < 32){
    int ap = sapix;
    sA[t] = g_B[(size_t)ap*CC + t];
    sD[t] = g_D[(size_t)ap*CC + t];
  }
  // per-thread negative sampling (exact threefry layout: uniform (Q,NEG,7))
  uint2 keyi = tf2(0u, 42u, 0u, (uint32_t)i);
  uint2 kb = tf2(keyi.x, keyi.y, 0u, 1u);
  uint2 kc = tf2(keyi.x, keyi.y, 0u, 2u);
  uint32_t base = ((uint32_t)q*256u + (uint32_t)t)*7u;
  int best = 0; float bs = POS_INF;
  #pragma unroll
  for (int jj=0; jj<7; jj++){
    uint2 bb = tf2(kb.x, kb.y, 0u, base + (uint32_t)jj);
    float u = u01f(bb.x ^ bb.y);
    float f = fmaxf(u + TINYF, TINYF);
    float score = (-logf(f)) * w7s[jj];   // argmin == argmax(gumbel+logit)
    if (score < bs){ bs = score; best = jj; }
  }
  int nc  = (i + 1 + best) & 7;
  int cntc = scnt8[nc];
  uint2 b3 = tf2(kc.x, kc.y, 0u, (uint32_t)(q*256 + t));
  float u3 = u01f(b3.x ^ b3.y);
  int r = (int)(u3 * (float)cntc);
  int rm = cntc - 1; if (rm < 0) rm = 0;
  if (r > rm) r = rm;
  snp[t] = g_tblV[nc*TBLSTRIDE + r];
  __syncthreads();
  // MLS logits: 257 rows, warp per row batch, lane = channel
  int w = t>>5, c = t&31;
  float A = sA[c], Da = sD[c];
  for (int j = w; j < 257; j += 8){
    float Bv, Dv;
    if (j == 0){ Bv = g_posB[i*CC+c]; Dv = g_posD[i*CC+c]; }
    else { int p = snp[j-1]; Bv = g_B[(size_t)p*CC+c]; Dv = g_D[(size_t)p*CC+c]; }
    float dn = Da + Dv;
    float d  = A - Bv;
    float part = __fdividef(d*d, dn) + __logf(dn);
    float tot = wsum32(part);
    if (c == 0) sl[j] = -tot*(1.0f/32.0f);   // -0.5*mean/TEMP
  }
  __syncthreads();
  float v = sl[t]; if (t == 0) v = fmaxf(v, sl[256]);
  red[t] = v; __syncthreads();
  for (int o = 128; o; o >>= 1){ if (t < o) red[t] = fmaxf(red[t], red[t+o]); __syncthreads(); }
  float m = red[0]; __syncthreads();
  float ev = expf(sl[t]-m); if (t == 0) ev += expf(sl[256]-m);
  red[t] = ev; __syncthreads();
  for (int o = 128; o; o >>= 1){ if (t < o) red[t] += red[t+o]; __syncthreads(); }
  if (t == 0) g_ce[iq] = (logf(red[0]) + m) - sl[0];
}

// ---------------- K8: parallel final reduction ----------------
__global__ void k8_final(float* out){
  __shared__ float cls[8];
  int t = threadIdx.x, w = t>>5, lane = t&31;
  float s = 0.0f;
  #pragma unroll
  for (int k = 0; k < 8; k++) s += g_ce[w*QQ + k*32 + lane];
  s = wsum32(s);
  if (lane == 0) cls[w] = s * (1.0f/(float)QQ);
  __syncthreads();
  if (t == 0){
    int vn = 0; float tot = 0.0f;
    for (int i = 0; i < SS; i++) if (g_countV[i] > 0) vn++;
    for (int i = 0; i < SS; i++)
      if (g_countV[i] > 0 && g_countH[i] > 0) tot += cls[i];
    out[0] = tot / (float)(vn > 0 ? vn : 1);
  }
}

extern "C" void kernel_launch(void* const* d_in, const int* in_sizes, int n_in,
                              void* d_out, int out_size){
  const float* W  = (const float*)d_in[0];
  const float* MU = (const float*)d_in[1];
  const float* SG = (const float*)d_in[2];
  const float* LB = (const float*)d_in[3];
  const float* MK = (const float*)d_in[4];
  const float* PR = (const float*)d_in[5];
  float* out = (float*)d_out;
  k1_classify<<<NCHUNK,256>>>(LB, MK, PR);
  k2_transpose<<<NN/64,256>>>(W, MU, SG);
  k3_scan<<<1,512>>>();
  k3b_rank<<<NCHUNK,32>>>();
  k4_proto<<<1,256>>>();
  k567_mls<<<SS*QQ,256>>>();
  k8_final<<<1,256>>>(out);
}

// round 11
// speedup vs baseline: 1.6242x; 1.1835x over previous
#include <cuda_runtime.h>
#include <cuda_bf16.h>
#include <stdint.h>
#include <math.h>

#define BB 4
#define CC 32
#define HWPIX 65536
#define SS 8
#define NN 262144
#define QQ 256
#define NEGS 256
#define NCHUNK 256
#define CHUNK 1024
#define TBLSTRIDE 32768
#define FPSCALE 16777216.0f
#define INV_FPSCALE (1.0/16777216.0)
#define TINYF 1.17549435e-38f
#define NEG_INF (__int_as_float(0xFF800000))
#define POS_INF (__int_as_float(0x7F800000))

// ---------------- device scratch ----------------
__device__ uint8_t g_cls[NN];
__device__ int g_chunkCntV[SS*NCHUNK];
__device__ int g_chunkCntH[SS*NCHUNK];
__device__ int g_offV[SS*NCHUNK];
__device__ int g_offH[SS*NCHUNK];
__device__ int g_countV[SS];
__device__ int g_countH[SS];
__device__ unsigned long long g_protoLL[SS*CC*3];
__device__ float g_B[(size_t)NN*CC];   // l2norm(mu)*w
__device__ float g_D[(size_t)NN*CC];   // sigma*w
__device__ int g_tblV[SS*TBLSTRIDE];
__device__ int g_tblH[SS*TBLSTRIDE];
__device__ float g_w7[SS*7];
__device__ float g_posB[SS*CC];
__device__ float g_posD[SS*CC];
__device__ float g_ce[SS*QQ];

// ---------------- JAX threefry2x32 (exact) ----------------
__device__ __forceinline__ uint2 tf2(uint32_t k0, uint32_t k1, uint32_t c0, uint32_t c1){
  uint32_t ks2 = k0 ^ k1 ^ 0x1BD11BDAu;
  uint32_t x0 = c0 + k0;
  uint32_t x1 = c1 + k1;
#define TFR(d) { x0 += x1; x1 = ((x1 << (d)) | (x1 >> (32-(d)))); x1 ^= x0; }
  TFR(13) TFR(15) TFR(26) TFR(6)
  x0 += k1;  x1 += ks2 + 1u;
  TFR(17) TFR(29) TFR(16) TFR(24)
  x0 += ks2; x1 += k0 + 2u;
  TFR(13) TFR(15) TFR(26) TFR(6)
  x0 += k0;  x1 += k1 + 3u;
  TFR(17) TFR(29) TFR(16) TFR(24)
  x0 += k1;  x1 += ks2 + 4u;
  TFR(13) TFR(15) TFR(26) TFR(6)
  x0 += ks2; x1 += k0 + 5u;
#undef TFR
  return make_uint2(x0, x1);
}
__device__ __forceinline__ float u01f(uint32_t bits){
  return __uint_as_float((bits >> 9) | 0x3F800000u) - 1.0f;
}
__device__ __forceinline__ float wsum32(float v){
  #pragma unroll
  for (int d = 16; d; d >>= 1) v += __shfl_xor_sync(0xFFFFFFFFu, v, d);
  return v;
}

// ---------------- K1: classify pixels + per-chunk counts (+clear protos) ----------------
__global__ void k1_classify(const float* __restrict__ label,
                            const float* __restrict__ mask,
                            const float* __restrict__ prob){
  __shared__ int cV[SS], cH[SS];
  if (blockIdx.x == 0){
    for (int i = threadIdx.x; i < SS*CC*3; i += 256) g_protoLL[i] = 0ull;
  }
  if (threadIdx.x < SS){ cV[threadIdx.x] = 0; cH[threadIdx.x] = 0; }
  __syncthreads();
  int chunk = blockIdx.x;
  for (int k = 0; k < CHUNK/256; k++){
    int n = chunk*CHUNK + k*256 + threadIdx.x;
    int b = n >> 16, hw = n & (HWPIX-1);
    float mk = mask[b*HWPIX + hw];
    int cls = -1;
    #pragma unroll
    for (int s = 0; s < SS; s++){
      float lv = label[((size_t)b*SS + s)*HWPIX + hw];
      if (lv > 0.0f) cls = s;
    }
    uint8_t byte = 0xFF;
    if (mk > 0.0f && cls >= 0){
      float p = prob[((size_t)b*SS + cls)*HWPIX + hw];
      int hard = (p < 0.97f) ? 1 : 0;
      byte = (uint8_t)(cls | (hard << 4));
      atomicAdd(&cV[cls], 1);
      if (hard) atomicAdd(&cH[cls], 1);
    }
    g_cls[n] = byte;
  }
  __syncthreads();
  if (threadIdx.x < SS){
    g_chunkCntV[threadIdx.x*NCHUNK + chunk] = cV[threadIdx.x];
    g_chunkCntH[threadIdx.x*NCHUNK + chunk] = cH[threadIdx.x];
  }
}

// ---------------- K2: transpose -> B/D vectors + fixed-point proto sums ----------------
__global__ void k2_transpose(const float* __restrict__ W,
                             const float* __restrict__ MU,
                             const float* __restrict__ SG){
  __shared__ float sw[32*65], smu[32*65], ssg[32*65];
  __shared__ unsigned long long acc[SS*CC*3];
  __shared__ uint8_t scls[64];
  int t = threadIdx.x;
  for (int i = t; i < SS*CC*3; i += 256) acc[i] = 0ull;
  int n0 = blockIdx.x * 64;
  int b = n0 >> 16, hw0 = n0 & (HWPIX-1);
  size_t base = (size_t)b*CC*HWPIX + hw0;
  for (int idx = t; idx < 2048; idx += 256){
    int c = idx >> 6, p = idx & 63;
    size_t gidx = base + (size_t)c*HWPIX + p;
    sw[c*65+p]  = W[gidx];
    smu[c*65+p] = MU[gidx];
    ssg[c*65+p] = SG[gidx];
  }
  if (t < 64) scls[t] = g_cls[n0 + t];
  __syncthreads();
  int c = t & 31, p0 = t >> 5;
  for (int p = p0; p < 64; p += 8){
    float w  = sw[c*65+p];
    float mu = smu[c*65+p];
    float sg = ssg[c*65+p];
    float nrm = sqrtf(wsum32(mu*mu));
    float mun = mu / fmaxf(nrm, 1e-12f);
    size_t o = (size_t)(n0 + p)*CC + c;
    g_B[o] = mun * w;
    g_D[o] = sg * w;
    uint8_t cb = scls[p];
    if (cb != 0xFF){
      int s = cb & 7;
      float isw = w / sg;
      float iw  = 1.0f / w;
      long long a0 = llrintf(isw * FPSCALE);
      long long a1 = llrintf((isw * mu) * FPSCALE);
      long long a2 = llrintf(iw * FPSCALE);
      atomicAdd(&acc[(s*CC + c)*3 + 0], (unsigned long long)a0);
      atomicAdd(&acc[(s*CC + c)*3 + 1], (unsigned long long)a1);
      atomicAdd(&acc[(s*CC + c)*3 + 2], (unsigned long long)a2);
    }
  }
  __syncthreads();
  for (int i = t; i < SS*CC*3; i += 256)
    if (acc[i]) atomicAdd(&g_protoLL[i], acc[i]);
}

// ---------------- K34: fused chunk-offset scan (warps 0-15) + prototypes (threads 0-255) ----------------
__global__ void k34_scan_proto(){
  __shared__ float sPB[8][32], sPD[8][32];
  __shared__ int scntV[8], scntH[8];
  int t = threadIdx.x, w = t>>5, lane = t&31;
  // ---- phase A: 16 warps scan chunk counts ----
  {
    int s = w >> 1; bool H = (w & 1);
    const int* cnt = H ? g_chunkCntH : g_chunkCntV;
    int* off = H ? g_offH : g_offV;
    int carry = 0;
    #pragma unroll
    for (int seg = 0; seg < 8; seg++){
      int v = cnt[s*NCHUNK + seg*32 + lane];
      int x = v;
      #pragma unroll
      for (int d = 1; d < 32; d <<= 1){
        int y = __shfl_up_sync(0xFFFFFFFFu, x, d);
        if (lane >= d) x += y;
      }
      off[s*NCHUNK + seg*32 + lane] = carry + x - v;
      carry += __shfl_sync(0xFFFFFFFFu, x, 31);
    }
    if (lane == 0){
      if (H){ g_countH[s] = carry; scntH[s] = carry; }
      else  { g_countV[s] = carry; scntV[s] = carry; }
    }
  }
  __syncthreads();
  // ---- phase B: prototypes + categorical weights (first 8 warps) ----
  if (t < 256){
    int s = w, c = lane;
    long long a0 = (long long)g_protoLL[(s*CC+c)*3+0];
    long long a1 = (long long)g_protoLL[(s*CC+c)*3+1];
    long long a2 = (long long)g_protoLL[(s*CC+c)*3+2];
    float sA = (float)((double)a0*INV_FPSCALE);
    float sB = (float)((double)a1*INV_FPSCALE);
    float sC = (float)((double)a2*INV_FPSCALE);
    float psig = 1.0f/sA;
    float pmu  = psig*sB;
    float pw   = 1.0f/sC;
    float nrm = sqrtf(wsum32(pmu*pmu));
    float pn = pmu / fmaxf(nrm, 1e-12f);
    float pb = pn*pw, pd = psig*pw;
    sPB[s][c]=pb; sPD[s][c]=pd;
    g_posB[s*CC+c]=pb; g_posD[s*CC+c]=pd;
    __syncwarp();
  }
  __syncthreads();
  if (t < 256){
    int s = w, c = lane;
    float Lv[7];
    for (int jj=0; jj<7; jj++){
      int j = (s+1+jj)&7;
      float d  = sPB[s][c]-sPB[j][c];
      float dn = sPD[s][c]+sPD[j][c];
      float part = d*d/dn + logf(dn);
      float tot = wsum32(part);
      if (c==0){
        float sim = -0.5f*(tot/32.0f);
        Lv[jj] = (scntV[j]>0) ? sim*2.0f : NEG_INF;   // /TEMP
      }
    }
    if (c==0){
      float Lmax = NEG_INF;
      #pragma unroll
      for (int jj=0;jj<7;jj++) Lmax = fmaxf(Lmax, Lv[jj]);
      #pragma unroll
      for (int jj=0;jj<7;jj++){
        float a = -(Lv[jj]-Lmax);
        if (!(a < 80.0f)) a = 80.0f;
        g_w7[s*7+jj] = expf(a);
      }
    }
  }
}

// ---------------- K3b: stable rank tables, 8 warps/chunk, two-phase ----------------
__global__ void k3b_rank(){
  __shared__ int scV[8][8], scH[8][8];   // [warp][class]
  int chunk = blockIdx.x;
  int t = threadIdx.x, w = t>>5, lane = t&31;
  unsigned lt = (1u<<lane)-1u;
  // each warp handles 4 groups of 32 pixels
  uint8_t byt[4];
  int cV[8], cH[8];
  #pragma unroll
  for (int s=0;s<8;s++){ cV[s]=0; cH[s]=0; }
  #pragma unroll
  for (int g=0; g<4; g++){
    int n = chunk*CHUNK + w*128 + g*32 + lane;
    byt[g] = g_cls[n];
    bool val = (byt[g] != 0xFF);
    int myc = byt[g] & 7;
    bool hrd = val && (byt[g] & 16);
    #pragma unroll
    for (int s=0;s<8;s++){
      cV[s] += __popc(__ballot_sync(0xFFFFFFFFu, val && myc==s));
      cH[s] += __popc(__ballot_sync(0xFFFFFFFFu, hrd && myc==s));
    }
  }
  if (lane < 8){ scV[w][lane] = cV[lane]; scH[w][lane] = cH[lane]; }
  __syncthreads();
  int baseV[8], baseH[8];
  #pragma unroll
  for (int s=0;s<8;s++){
    int bv = g_offV[s*NCHUNK+chunk], bh = g_offH[s*NCHUNK+chunk];
    for (int ww=0; ww<w; ww++){ bv += scV[ww][s]; bh += scH[ww][s]; }
    baseV[s]=bv; baseH[s]=bh;
  }
  int rcV[8], rcH[8];
  #pragma unroll
  for (int s=0;s<8;s++){ rcV[s]=0; rcH[s]=0; }
  #pragma unroll
  for (int g=0; g<4; g++){
    int n = chunk*CHUNK + w*128 + g*32 + lane;
    bool val = (byt[g] != 0xFF);
    int myc = byt[g] & 7;
    bool hrd = val && (byt[g] & 16);
    #pragma unroll
    for (int s=0;s<8;s++){
      unsigned mV = __ballot_sync(0xFFFFFFFFu, val && myc==s);
      unsigned mH = __ballot_sync(0xFFFFFFFFu, hrd && myc==s);
      if (val && myc==s){
        g_tblV[s*TBLSTRIDE + baseV[s] + rcV[s] + __popc(mV&lt)] = n;
        if (hrd) g_tblH[s*TBLSTRIDE + baseH[s] + rcH[s] + __popc(mH&lt)] = n;
      }
      rcV[s] += __popc(mV); rcH[s] += __popc(mH);
    }
  }
}

// ---------------- K567: anchor + negatives + MLS logits + logsumexp (fused) ----------------
__global__ void k567_mls(){
  __shared__ float sA[32], sD[32], sl[257], red[256], w7s[7];
  __shared__ int snp[256], scnt8[8], sapix;
  __shared__ uint32_t skey[4];           // kb.x kb.y kc.x kc.y
  int iq = blockIdx.x; int i = iq>>8, q = iq&255; int t = threadIdx.x;
  if (t < 8) scnt8[t] = g_countV[t];
  if (t < 7) w7s[t] = g_w7[i*7+t];
  if (t == 0){
    uint2 keyi = tf2(0u, 42u, 0u, (uint32_t)i);
    uint2 ka   = tf2(keyi.x, keyi.y, 0u, 0u);
    uint2 kb   = tf2(keyi.x, keyi.y, 0u, 1u);
    uint2 kc   = tf2(keyi.x, keyi.y, 0u, 2u);
    skey[0]=kb.x; skey[1]=kb.y; skey[2]=kc.x; skey[3]=kc.y;
    uint2 bu   = tf2(ka.x, ka.y, 0u, (uint32_t)q);
    float u = u01f(bu.x ^ bu.y);
    int hc = g_countH[i];
    int r = (int)(u * (float)hc);
    int rm = hc - 1; if (rm < 0) rm = 0;
    if (r > rm) r = rm;
    sapix = g_tblH[i*TBLSTRIDE + r];
  }
  __syncthreads();
  if (t < 32){
    int ap = sapix;
    sA[t] = g_B[(size_t)ap*CC + t];
    sD[t] = g_D[(size_t)ap*CC + t];
  }
  // per-thread negative sampling (exact threefry layout: uniform (Q,NEG,7))
  uint32_t kbx = skey[0], kby = skey[1];
  uint32_t base = ((uint32_t)q*256u + (uint32_t)t)*7u;
  int best = 0; float bs = POS_INF;
  #pragma unroll
  for (int jj=0; jj<7; jj++){
    uint2 bb = tf2(kbx, kby, 0u, base + (uint32_t)jj);
    float u = u01f(bb.x ^ bb.y);
    float f = fmaxf(u + TINYF, TINYF);
    float score = (-logf(f)) * w7s[jj];   // argmin == argmax(gumbel+logit)
    if (score < bs){ bs = score; best = jj; }
  }
  int nc  = (i + 1 + best) & 7;
  int cntc = scnt8[nc];
  uint2 b3 = tf2(skey[2], skey[3], 0u, (uint32_t)(q*256 + t));
  float u3 = u01f(b3.x ^ b3.y);
  int r = (int)(u3 * (float)cntc);
  int rm = cntc - 1; if (rm < 0) rm = 0;
  if (r > rm) r = rm;
  snp[t] = g_tblV[nc*TBLSTRIDE + r];
  __syncthreads();
  // MLS logits: 257 rows, one warp per row, lane = channel
  int w = t>>5, c = t&31;
  float A = sA[c], Da = sD[c];
  for (int j = w; j < 257; j += 8){
    float Bv, Dv;
    if (j == 0){ Bv = g_posB[i*CC+c]; Dv = g_posD[i*CC+c]; }
    else { int p = snp[j-1]; Bv = g_B[(size_t)p*CC+c]; Dv = g_D[(size_t)p*CC+c]; }
    float dn = Da + Dv;
    float d  = A - Bv;
    float part = __fdividef(d*d, dn) + __logf(dn);
    float tot = wsum32(part);
    if (c == 0) sl[j] = -tot*(1.0f/32.0f);   // -0.5*mean/TEMP
  }
  __syncthreads();
  float v = sl[t]; if (t == 0) v = fmaxf(v, sl[256]);
  red[t] = v; __syncthreads();
  for (int o = 128; o; o >>= 1){ if (t < o) red[t] = fmaxf(red[t], red[t+o]); __syncthreads(); }
  float m = red[0]; __syncthreads();
  float ev = expf(sl[t]-m); if (t == 0) ev += expf(sl[256]-m);
  red[t] = ev; __syncthreads();
  for (int o = 128; o; o >>= 1){ if (t < o) red[t] += red[t+o]; __syncthreads(); }
  if (t == 0) g_ce[iq] = (logf(red[0]) + m) - sl[0];
}

// ---------------- K8: parallel final reduction ----------------
__global__ void k8_final(float* out){
  __shared__ float cls[8];
  int t = threadIdx.x, w = t>>5, lane = t&31;
  float s = 0.0f;
  #pragma unroll
  for (int k = 0; k < 8; k++) s += g_ce[w*QQ + k*32 + lane];
  s = wsum32(s);
  if (lane == 0) cls[w] = s * (1.0f/(float)QQ);
  __syncthreads();
  if (t == 0){
    int vn = 0; float tot = 0.0f;
    for (int i = 0; i < SS; i++) if (g_countV[i] > 0) vn++;
    for (int i = 0; i < SS; i++)
      if (g_countV[i] > 0 && g_countH[i] > 0) tot += cls[i];
    out[0] = tot / (float)(vn > 0 ? vn : 1);
  }
}

extern "C" void kernel_launch(void* const* d_in, const int* in_sizes, int n_in,
                              void* d_out, int out_size){
  const float* W  = (const float*)d_in[0];
  const float* MU = (const float*)d_in[1];
  const float* SG = (const float*)d_in[2];
  const float* LB = (const float*)d_in[3];
  const float* MK = (const float*)d_in[4];
  const float* PR = (const float*)d_in[5];
  float* out = (float*)d_out;
  k1_classify<<<NCHUNK,256>>>(LB, MK, PR);
  k2_transpose<<<NN/64,256>>>(W, MU, SG);
  k34_scan_proto<<<1,512>>>();
  k3b_rank<<<NCHUNK,256>>>();
  k567_mls<<<SS*QQ,256>>>();
  k8_final<<<1,256>>>(out);
}

// round 12
// speedup vs baseline: 1.7031x; 1.0486x over previous
#include <cuda_runtime.h>
#include <cuda_bf16.h>
#include <stdint.h>
#include <math.h>

#define BB 4
#define CC 32
#define HWPIX 65536
#define SS 8
#define NN 262144
#define QQ 256
#define NEGS 256
#define NCHUNK 256
#define CHUNK 1024
#define TBLSTRIDE 32768
#define FPSCALE 16777216.0f
#define INV_FPSCALE (1.0/16777216.0)
#define TINYF 1.17549435e-38f
#define NEG_INF (__int_as_float(0xFF800000))
#define POS_INF (__int_as_float(0x7F800000))

// ---------------- device scratch ----------------
__device__ uint8_t g_cls[NN];
__device__ int g_chunkCntV[SS*NCHUNK];
__device__ int g_chunkCntH[SS*NCHUNK];
__device__ int g_offV[SS*NCHUNK];
__device__ int g_offH[SS*NCHUNK];
__device__ int g_countV[SS];
__device__ int g_countH[SS];
__device__ unsigned long long g_protoLL[SS*CC*3];
__device__ float g_B[(size_t)NN*CC];   // l2norm(mu)*w
__device__ float g_D[(size_t)NN*CC];   // sigma*w
__device__ int g_tblV[SS*TBLSTRIDE];
__device__ int g_tblH[SS*TBLSTRIDE];
__device__ float g_w7[SS*7];
__device__ float g_posB[SS*CC];
__device__ float g_posD[SS*CC];
__device__ float g_ce[SS*QQ];

// ---------------- JAX threefry2x32 (exact) ----------------
__device__ __forceinline__ uint2 tf2(uint32_t k0, uint32_t k1, uint32_t c0, uint32_t c1){
  uint32_t ks2 = k0 ^ k1 ^ 0x1BD11BDAu;
  uint32_t x0 = c0 + k0;
  uint32_t x1 = c1 + k1;
#define TFR(d) { x0 += x1; x1 = ((x1 << (d)) | (x1 >> (32-(d)))); x1 ^= x0; }
  TFR(13) TFR(15) TFR(26) TFR(6)
  x0 += k1;  x1 += ks2 + 1u;
  TFR(17) TFR(29) TFR(16) TFR(24)
  x0 += ks2; x1 += k0 + 2u;
  TFR(13) TFR(15) TFR(26) TFR(6)
  x0 += k0;  x1 += k1 + 3u;
  TFR(17) TFR(29) TFR(16) TFR(24)
  x0 += k1;  x1 += ks2 + 4u;
  TFR(13) TFR(15) TFR(26) TFR(6)
  x0 += ks2; x1 += k0 + 5u;
#undef TFR
  return make_uint2(x0, x1);
}
__device__ __forceinline__ float u01f(uint32_t bits){
  return __uint_as_float((bits >> 9) | 0x3F800000u) - 1.0f;
}
__device__ __forceinline__ float wsum32(float v){
  #pragma unroll
  for (int d = 16; d; d >>= 1) v += __shfl_xor_sync(0xFFFFFFFFu, v, d);
  return v;
}
__device__ __forceinline__ float wmax32(float v){
  #pragma unroll
  for (int d = 16; d; d >>= 1) v = fmaxf(v, __shfl_xor_sync(0xFFFFFFFFu, v, d));
  return v;
}

// ---------------- K1: classify pixels + per-chunk counts (+clear protos) ----------------
__global__ void k1_classify(const float* __restrict__ label,
                            const float* __restrict__ mask,
                            const float* __restrict__ prob){
  __shared__ int cV[SS], cH[SS];
  if (blockIdx.x == 0){
    for (int i = threadIdx.x; i < SS*CC*3; i += 256) g_protoLL[i] = 0ull;
  }
  if (threadIdx.x < SS){ cV[threadIdx.x] = 0; cH[threadIdx.x] = 0; }
  __syncthreads();
  int chunk = blockIdx.x;
  for (int k = 0; k < CHUNK/256; k++){
    int n = chunk*CHUNK + k*256 + threadIdx.x;
    int b = n >> 16, hw = n & (HWPIX-1);
    float mk = mask[b*HWPIX + hw];
    int cls = -1;
    #pragma unroll
    for (int s = 0; s < SS; s++){
      float lv = label[((size_t)b*SS + s)*HWPIX + hw];
      if (lv > 0.0f) cls = s;
    }
    uint8_t byte = 0xFF;
    if (mk > 0.0f && cls >= 0){
      float p = prob[((size_t)b*SS + cls)*HWPIX + hw];
      int hard = (p < 0.97f) ? 1 : 0;
      byte = (uint8_t)(cls | (hard << 4));
      atomicAdd(&cV[cls], 1);
      if (hard) atomicAdd(&cH[cls], 1);
    }
    g_cls[n] = byte;
  }
  __syncthreads();
  if (threadIdx.x < SS){
    g_chunkCntV[threadIdx.x*NCHUNK + chunk] = cV[threadIdx.x];
    g_chunkCntH[threadIdx.x*NCHUNK + chunk] = cH[threadIdx.x];
  }
}

// ---------------- K2: transpose -> B/D vectors + fixed-point proto sums ----------------
__global__ void k2_transpose(const float* __restrict__ W,
                             const float* __restrict__ MU,
                             const float* __restrict__ SG){
  __shared__ float sw[32*65], smu[32*65], ssg[32*65];
  __shared__ unsigned long long acc[SS*CC*3];
  __shared__ uint8_t scls[64];
  int t = threadIdx.x;
  for (int i = t; i < SS*CC*3; i += 256) acc[i] = 0ull;
  int n0 = blockIdx.x * 64;
  int b = n0 >> 16, hw0 = n0 & (HWPIX-1);
  size_t base = (size_t)b*CC*HWPIX + hw0;
  for (int idx = t; idx < 2048; idx += 256){
    int c = idx >> 6, p = idx & 63;
    size_t gidx = base + (size_t)c*HWPIX + p;
    sw[c*65+p]  = W[gidx];
    smu[c*65+p] = MU[gidx];
    ssg[c*65+p] = SG[gidx];
  }
  if (t < 64) scls[t] = g_cls[n0 + t];
  __syncthreads();
  int c = t & 31, p0 = t >> 5;
  for (int p = p0; p < 64; p += 8){
    float w  = sw[c*65+p];
    float mu = smu[c*65+p];
    float sg = ssg[c*65+p];
    float nrm = sqrtf(wsum32(mu*mu));
    float mun = mu / fmaxf(nrm, 1e-12f);
    size_t o = (size_t)(n0 + p)*CC + c;
    g_B[o] = mun * w;
    g_D[o] = sg * w;
    uint8_t cb = scls[p];
    if (cb != 0xFF){
      int s = cb & 7;
      float isw = w / sg;
      float iw  = 1.0f / w;
      long long a0 = llrintf(isw * FPSCALE);
      long long a1 = llrintf((isw * mu) * FPSCALE);
      long long a2 = llrintf(iw * FPSCALE);
      atomicAdd(&acc[(s*CC + c)*3 + 0], (unsigned long long)a0);
      atomicAdd(&acc[(s*CC + c)*3 + 1], (unsigned long long)a1);
      atomicAdd(&acc[(s*CC + c)*3 + 2], (unsigned long long)a2);
    }
  }
  __syncthreads();
  for (int i = t; i < SS*CC*3; i += 256)
    if (acc[i]) atomicAdd(&g_protoLL[i], acc[i]);
}

// ---------------- K34: fused chunk-offset scan + prototypes ----------------
__global__ void k34_scan_proto(){
  __shared__ float sPB[8][32], sPD[8][32];
  __shared__ int scntV[8];
  int t = threadIdx.x, w = t>>5, lane = t&31;
  {
    int s = w >> 1; bool H = (w & 1);
    const int* cnt = H ? g_chunkCntH : g_chunkCntV;
    int* off = H ? g_offH : g_offV;
    int carry = 0;
    #pragma unroll
    for (int seg = 0; seg < 8; seg++){
      int v = cnt[s*NCHUNK + seg*32 + lane];
      int x = v;
      #pragma unroll
      for (int d = 1; d < 32; d <<= 1){
        int y = __shfl_up_sync(0xFFFFFFFFu, x, d);
        if (lane >= d) x += y;
      }
      off[s*NCHUNK + seg*32 + lane] = carry + x - v;
      carry += __shfl_sync(0xFFFFFFFFu, x, 31);
    }
    if (lane == 0){
      if (H){ g_countH[s] = carry; }
      else  { g_countV[s] = carry; scntV[s] = carry; }
    }
  }
  __syncthreads();
  if (t < 256){
    int s = w, c = lane;
    long long a0 = (long long)g_protoLL[(s*CC+c)*3+0];
    long long a1 = (long long)g_protoLL[(s*CC+c)*3+1];
    long long a2 = (long long)g_protoLL[(s*CC+c)*3+2];
    float sA = (float)((double)a0*INV_FPSCALE);
    float sB = (float)((double)a1*INV_FPSCALE);
    float sC = (float)((double)a2*INV_FPSCALE);
    float psig = 1.0f/sA;
    float pmu  = psig*sB;
    float pw   = 1.0f/sC;
    float nrm = sqrtf(wsum32(pmu*pmu));
    float pn = pmu / fmaxf(nrm, 1e-12f);
    float pb = pn*pw, pd = psig*pw;
    sPB[s][c]=pb; sPD[s][c]=pd;
    g_posB[s*CC+c]=pb; g_posD[s*CC+c]=pd;
    __syncwarp();
  }
  __syncthreads();
  if (t < 256){
    int s = w, c = lane;
    float Lv[7];
    for (int jj=0; jj<7; jj++){
      int j = (s+1+jj)&7;
      float d  = sPB[s][c]-sPB[j][c];
      float dn = sPD[s][c]+sPD[j][c];
      float part = d*d/dn + logf(dn);
      float tot = wsum32(part);
      if (c==0){
        float sim = -0.5f*(tot/32.0f);
        Lv[jj] = (scntV[j]>0) ? sim*2.0f : NEG_INF;   // /TEMP
      }
    }
    if (c==0){
      float Lmax = NEG_INF;
      #pragma unroll
      for (int jj=0;jj<7;jj++) Lmax = fmaxf(Lmax, Lv[jj]);
      #pragma unroll
      for (int jj=0;jj<7;jj++){
        float a = -(Lv[jj]-Lmax);
        if (!(a < 80.0f)) a = 80.0f;
        g_w7[s*7+jj] = expf(a);
      }
    }
  }
}

// ---------------- K3b: stable rank tables via match_any, 8 warps/chunk ----------------
__global__ void k3b_rank(){
  __shared__ int scV[8][8], scH[8][8];     // pass-1 per-warp per-class counts
  __shared__ int runV[8][8], runH[8][8];   // pass-2 running bases
  int chunk = blockIdx.x;
  int t = threadIdx.x, w = t>>5, lane = t&31;
  unsigned lt = (1u<<lane)-1u;
  if (lane < 8){ scV[w][lane] = 0; scH[w][lane] = 0; }
  uint8_t byt[4];
  // ---- pass 1: per-warp per-class counts ----
  #pragma unroll
  for (int g=0; g<4; g++){
    int n = chunk*CHUNK + w*128 + g*32 + lane;
    byt[g] = g_cls[n];
    bool val = (byt[g] != 0xFF);
    int cls = byt[g] & 7;
    int key = val ? cls : (256 + lane);            // invalid -> singleton
    unsigned mV = __match_any_sync(0xFFFFFFFFu, key);
    unsigned mH = mV & __ballot_sync(0xFFFFFFFFu, val && (byt[g] & 16));
    if (val){
      int leader = __ffs(mV) - 1;
      if (lane == leader){
        scV[w][cls] += __popc(mV);
        scH[w][cls] += __popc(mH);
      }
    }
    __syncwarp();
  }
  __syncthreads();
  // per-warp bases = chunk offset + prefix over earlier warps
  if (lane < 8){
    int bv = g_offV[lane*NCHUNK+chunk], bh = g_offH[lane*NCHUNK+chunk];
    for (int ww=0; ww<w; ww++){ bv += scV[ww][lane]; bh += scH[ww][lane]; }
    runV[w][lane] = bv; runH[w][lane] = bh;
  }
  __syncwarp();
  // ---- pass 2: stable scatter ----
  #pragma unroll
  for (int g=0; g<4; g++){
    int n = chunk*CHUNK + w*128 + g*32 + lane;
    bool val = (byt[g] != 0xFF);
    int cls = byt[g] & 7;
    bool hrd = val && (byt[g] & 16);
    int key = val ? cls : (256 + lane);
    unsigned mV = __match_any_sync(0xFFFFFFFFu, key);
    unsigned mH = mV & __ballot_sync(0xFFFFFFFFu, hrd);
    int leader = __ffs(mV) - 1;
    int baseV = 0, baseH = 0;
    if (val && lane == leader){
      baseV = runV[w][cls]; runV[w][cls] = baseV + __popc(mV);
      baseH = runH[w][cls]; runH[w][cls] = baseH + __popc(mH);
    }
    __syncwarp();
    baseV = __shfl_sync(0xFFFFFFFFu, baseV, leader);
    baseH = __shfl_sync(0xFFFFFFFFu, baseH, leader);
    if (val){
      g_tblV[cls*TBLSTRIDE + baseV + __popc(mV & lt)] = n;
      if (hrd) g_tblH[cls*TBLSTRIDE + baseH + __popc(mH & lt)] = n;
    }
    __syncwarp();
  }
}

// ---------------- K567: anchor + negatives + MLS logits + logsumexp (fused) ----------------
__global__ void k567_mls(){
  __shared__ float sA[32], sD[32], sl[257], w7s[7], sred[8], sM;
  __shared__ int snp[256], scnt8[8], sapix;
  __shared__ uint32_t skey[4];           // kb.x kb.y kc.x kc.y
  int iq = blockIdx.x; int i = iq>>8, q = iq&255; int t = threadIdx.x;
  if (t < 8) scnt8[t] = g_countV[t];
  if (t < 7) w7s[t] = g_w7[i*7+t];
  if (t == 0){
    uint2 keyi = tf2(0u, 42u, 0u, (uint32_t)i);
    uint2 ka   = tf2(keyi.x, keyi.y, 0u, 0u);
    uint2 kb   = tf2(keyi.x, keyi.y, 0u, 1u);
    uint2 kc   = tf2(keyi.x, keyi.y, 0u, 2u);
    skey[0]=kb.x; skey[1]=kb.y; skey[2]=kc.x; skey[3]=kc.y;
    uint2 bu   = tf2(ka.x, ka.y, 0u, (uint32_t)q);
    float u = u01f(bu.x ^ bu.y);
    int hc = g_countH[i];
    int r = (int)(u * (float)hc);
    int rm = hc - 1; if (rm < 0) rm = 0;
    if (r > rm) r = rm;
    sapix = g_tblH[i*TBLSTRIDE + r];
  }
  __syncthreads();
  if (t < 32){
    int ap = sapix;
    sA[t] = g_B[(size_t)ap*CC + t];
    sD[t] = g_D[(size_t)ap*CC + t];
  }
  // per-thread negative sampling (exact threefry layout: uniform (Q,NEG,7))
  uint32_t kbx = skey[0], kby = skey[1];
  uint32_t base = ((uint32_t)q*256u + (uint32_t)t)*7u;
  int best = 0; float bs = POS_INF;
  #pragma unroll
  for (int jj=0; jj<7; jj++){
    uint2 bb = tf2(kbx, kby, 0u, base + (uint32_t)jj);
    float u = u01f(bb.x ^ bb.y);
    float f = fmaxf(u + TINYF, TINYF);
    float score = (-__logf(f)) * w7s[jj];   // argmin == argmax(gumbel+logit)
    if (score < bs){ bs = score; best = jj; }
  }
  int nc  = (i + 1 + best) & 7;
  int cntc = scnt8[nc];
  uint2 b3 = tf2(skey[2], skey[3], 0u, (uint32_t)(q*256 + t));
  float u3 = u01f(b3.x ^ b3.y);
  int r = (int)(u3 * (float)cntc);
  int rm = cntc - 1; if (rm < 0) rm = 0;
  if (r > rm) r = rm;
  snp[t] = g_tblV[nc*TBLSTRIDE + r];
  __syncthreads();
  // MLS logits: 257 rows, one warp per row, lane = channel
  int w = t>>5, c = t&31;
  float A = sA[c], Da = sD[c];
  for (int j = w; j < 257; j += 8){
    float Bv, Dv;
    if (j == 0){ Bv = g_posB[i*CC+c]; Dv = g_posD[i*CC+c]; }
    else { int p = snp[j-1]; Bv = g_B[(size_t)p*CC+c]; Dv = g_D[(size_t)p*CC+c]; }
    float dn = Da + Dv;
    float d  = A - Bv;
    float part = __fdividef(d*d, dn) + __logf(dn);
    float tot = wsum32(part);
    if (c == 0) sl[j] = -tot*(1.0f/32.0f);   // -0.5*mean/TEMP
  }
  __syncthreads();
  // logsumexp: warp-shuffle two-level reduction
  float v = sl[t]; if (t == 0) v = fmaxf(v, sl[256]);
  float m = wmax32(v);
  if (c == 0) sred[w] = m;
  __syncthreads();
  if (t == 0){
    float M = sred[0];
    #pragma unroll
    for (int k = 1; k < 8; k++) M = fmaxf(M, sred[k]);
    sM = M;
  }
  __syncthreads();
  float M = sM;
  float e = __expf(v - M); if (t == 0) e += __expf(sl[256] - M);
  float s = wsum32(e);
  if (c == 0) sred[w] = s;
  __syncthreads();
  if (t == 0){
    float S = 0.0f;
    #pragma unroll
    for (int k = 0; k < 8; k++) S += sred[k];
    g_ce[iq] = (logf(S) + M) - sl[0];
  }
}

// ---------------- K8: parallel final reduction ----------------
__global__ void k8_final(float* out){
  __shared__ float cls[8];
  int t = threadIdx.x, w = t>>5, lane = t&31;
  float s = 0.0f;
  #pragma unroll
  for (int k = 0; k < 8; k++) s += g_ce[w*QQ + k*32 + lane];
  s = wsum32(s);
  if (lane == 0) cls[w] = s * (1.0f/(float)QQ);
  __syncthreads();
  if (t == 0){
    int vn = 0; float tot = 0.0f;
    for (int i = 0; i < SS; i++) if (g_countV[i] > 0) vn++;
    for (int i = 0; i < SS; i++)
      if (g_countV[i] > 0 && g_countH[i] > 0) tot += cls[i];
    out[0] = tot / (float)(vn > 0 ? vn : 1);
  }
}

extern "C" void kernel_launch(void* const* d_in, const int* in_sizes, int n_in,
                              void* d_out, int out_size){
  const float* W  = (const float*)d_in[0];
  const float* MU = (const float*)d_in[1];
  const float* SG = (const float*)d_in[2];
  const float* LB = (const float*)d_in[3];
  const float* MK = (const float*)d_in[4];
  const float* PR = (const float*)d_in[5];
  float* out = (float*)d_out;
  k1_classify<<<NCHUNK,256>>>(LB, MK, PR);
  k2_transpose<<<NN/64,256>>>(W, MU, SG);
  k34_scan_proto<<<1,512>>>();
  k3b_rank<<<NCHUNK,256>>>();
  k567_mls<<<SS*QQ,256>>>();
  k8_final<<<1,256>>>(out);
}

// round 15
// speedup vs baseline: 1.7263x; 1.0137x over previous
#include <cuda_runtime.h>
#include <cuda_bf16.h>
#include <stdint.h>
#include <math.h>

#define BB 4
#define CC 32
#define HWPIX 65536
#define SS 8
#define NN 262144
#define QQ 256
#define NEGS 256
#define NCHUNK 256
#define CHUNK 1024
#define TBLSTRIDE 32768
#define FPSCALE 16777216.0f
#define INV_FPSCALE (1.0/16777216.0)
#define TINYF 1.17549435e-38f
#define NEG_INF (__int_as_float(0xFF800000))
#define POS_INF (__int_as_float(0x7F800000))

// ---------------- device scratch ----------------
__device__ uint8_t g_cls[NN];
__device__ int g_chunkCntV[SS*NCHUNK];
__device__ int g_chunkCntH[SS*NCHUNK];
__device__ int g_offV[SS*NCHUNK];
__device__ int g_offH[SS*NCHUNK];
__device__ int g_countV[SS];
__device__ int g_countH[SS];
__device__ unsigned long long g_protoLL[SS*CC*3];   // zero at load; re-zeroed at end of every call
__device__ float2 g_BD[(size_t)NN*CC];              // (l2norm(mu)*w, sigma*w) interleaved
__device__ int g_tblV[SS*TBLSTRIDE];
__device__ int g_tblH[SS*TBLSTRIDE];
__device__ float g_w7[SS*7];
__device__ float g_posB[SS*CC];
__device__ float g_posD[SS*CC];
__device__ float g_ce[SS*QQ];

// ---------------- JAX threefry2x32 (exact) ----------------
__device__ __forceinline__ uint2 tf2(uint32_t k0, uint32_t k1, uint32_t c0, uint32_t c1){
  uint32_t ks2 = k0 ^ k1 ^ 0x1BD11BDAu;
  uint32_t x0 = c0 + k0;
  uint32_t x1 = c1 + k1;
#define TFR(d) { x0 += x1; x1 = ((x1 << (d)) | (x1 >> (32-(d)))); x1 ^= x0; }
  TFR(13) TFR(15) TFR(26) TFR(6)
  x0 += k1;  x1 += ks2 + 1u;
  TFR(17) TFR(29) TFR(16) TFR(24)
  x0 += ks2; x1 += k0 + 2u;
  TFR(13) TFR(15) TFR(26) TFR(6)
  x0 += k0;  x1 += k1 + 3u;
  TFR(17) TFR(29) TFR(16) TFR(24)
  x0 += k1;  x1 += ks2 + 4u;
  TFR(13) TFR(15) TFR(26) TFR(6)
  x0 += ks2; x1 += k0 + 5u;
#undef TFR
  return make_uint2(x0, x1);
}
__device__ __forceinline__ float u01f(uint32_t bits){
  return __uint_as_float((bits >> 9) | 0x3F800000u) - 1.0f;
}
__device__ __forceinline__ float wsum32(float v){
  #pragma unroll
  for (int d = 16; d; d >>= 1) v += __shfl_xor_sync(0xFFFFFFFFu, v, d);
  return v;
}
__device__ __forceinline__ float wmax32(float v){
  #pragma unroll
  for (int d = 16; d; d >>= 1) v = fmaxf(v, __shfl_xor_sync(0xFFFFFFFFu, v, d));
  return v;
}

// ---------------- K1: classify pixels + per-chunk counts ----------------
__global__ void k1_classify(const float* __restrict__ label,
                            const float* __restrict__ mask,
                            const float* __restrict__ prob){
  __shared__ int cV[SS], cH[SS];
  if (threadIdx.x < SS){ cV[threadIdx.x] = 0; cH[threadIdx.x] = 0; }
  __syncthreads();
  int chunk = blockIdx.x;
  for (int k = 0; k < CHUNK/256; k++){
    int n = chunk*CHUNK + k*256 + threadIdx.x;
    int b = n >> 16, hw = n & (HWPIX-1);
    float mk = mask[b*HWPIX + hw];
    int cls = -1;
    #pragma unroll
    for (int s = 0; s < SS; s++){
      float lv = label[((size_t)b*SS + s)*HWPIX + hw];
      if (lv > 0.0f) cls = s;
    }
    uint8_t byte = 0xFF;
    if (mk > 0.0f && cls >= 0){
      float p = prob[((size_t)b*SS + cls)*HWPIX + hw];
      int hard = (p < 0.97f) ? 1 : 0;
      byte = (uint8_t)(cls | (hard << 4));
      atomicAdd(&cV[cls], 1);
      if (hard) atomicAdd(&cH[cls], 1);
    }
    g_cls[n] = byte;
  }
  __syncthreads();
  if (threadIdx.x < SS){
    g_chunkCntV[threadIdx.x*NCHUNK + chunk] = cV[threadIdx.x];
    g_chunkCntH[threadIdx.x*NCHUNK + chunk] = cH[threadIdx.x];
  }
}

// ---------------- K2: transpose -> interleaved BD + fixed-point proto sums ----------------
__global__ void k2_transpose(const float* __restrict__ W,
                             const float* __restrict__ MU,
                             const float* __restrict__ SG){
  __shared__ float sw[32*65], smu[32*65], ssg[32*65];
  __shared__ unsigned long long acc[SS*CC*3];
  __shared__ uint8_t scls[64];
  int t = threadIdx.x;
  for (int i = t; i < SS*CC*3; i += 256) acc[i] = 0ull;
  int n0 = blockIdx.x * 64;
  int b = n0 >> 16, hw0 = n0 & (HWPIX-1);
  size_t base = (size_t)b*CC*HWPIX + hw0;
  for (int idx = t; idx < 2048; idx += 256){
    int c = idx >> 6, p = idx & 63;
    size_t gidx = base + (size_t)c*HWPIX + p;
    sw[c*65+p]  = W[gidx];
    smu[c*65+p] = MU[gidx];
    ssg[c*65+p] = SG[gidx];
  }
  if (t < 64) scls[t] = g_cls[n0 + t];
  __syncthreads();
  int c = t & 31, p0 = t >> 5;
  for (int p = p0; p < 64; p += 8){
    float w  = sw[c*65+p];
    float mu = smu[c*65+p];
    float sg = ssg[c*65+p];
    float nrm = sqrtf(wsum32(mu*mu));
    float mun = mu / fmaxf(nrm, 1e-12f);
    g_BD[(size_t)(n0 + p)*CC + c] = make_float2(mun * w, sg * w);
    uint8_t cb = scls[p];
    if (cb != 0xFF){
      int s = cb & 7;
      float isw = w / sg;
      float iw  = 1.0f / w;
      long long a0 = llrintf(isw * FPSCALE);
      long long a1 = llrintf((isw * mu) * FPSCALE);
      long long a2 = llrintf(iw * FPSCALE);
      atomicAdd(&acc[(s*CC + c)*3 + 0], (unsigned long long)a0);
      atomicAdd(&acc[(s*CC + c)*3 + 1], (unsigned long long)a1);
      atomicAdd(&acc[(s*CC + c)*3 + 2], (unsigned long long)a2);
    }
  }
  __syncthreads();
  for (int i = t; i < SS*CC*3; i += 256)
    if (acc[i]) atomicAdd(&g_protoLL[i], acc[i]);
}

// ---------------- K34: fused chunk-offset scan + prototypes ----------------
__global__ void k34_scan_proto(){
  __shared__ float sPB[8][32], sPD[8][32];
  __shared__ int scntV[8];
  int t = threadIdx.x, w = t>>5, lane = t&31;
  {
    int s = w >> 1; bool H = (w & 1);
    const int* cnt = H ? g_chunkCntH : g_chunkCntV;
    int* off = H ? g_offH : g_offV;
    int carry = 0;
    #pragma unroll
    for (int seg = 0; seg < 8; seg++){
      int v = cnt[s*NCHUNK + seg*32 + lane];
      int x = v;
      #pragma unroll
      for (int d = 1; d < 32; d <<= 1){
        int y = __shfl_up_sync(0xFFFFFFFFu, x, d);
        if (lane >= d) x += y;
      }
      off[s*NCHUNK + seg*32 + lane] = carry + x - v;
      carry += __shfl_sync(0xFFFFFFFFu, x, 31);
    }
    if (lane == 0){
      if (H){ g_countH[s] = carry; }
      else  { g_countV[s] = carry; scntV[s] = carry; }
    }
  }
  __syncthreads();
  if (t < 256){
    int s = w, c = lane;
    long long a0 = (long long)g_protoLL[(s*CC+c)*3+0];
    long long a1 = (long long)g_protoLL[(s*CC+c)*3+1];
    long long a2 = (long long)g_protoLL[(s*CC+c)*3+2];
    float sA = (float)((double)a0*INV_FPSCALE);
    float sB = (float)((double)a1*INV_FPSCALE);
    float sC = (float)((double)a2*INV_FPSCALE);
    float psig = 1.0f/sA;
    float pmu  = psig*sB;
    float pw   = 1.0f/sC;
    float nrm = sqrtf(wsum32(pmu*pmu));
    float pn = pmu / fmaxf(nrm, 1e-12f);
    float pb = pn*pw, pd = psig*pw;
    sPB[s][c]=pb; sPD[s][c]=pd;
    g_posB[s*CC+c]=pb; g_posD[s*CC+c]=pd;
    __syncwarp();
  }
  __syncthreads();
  if (t < 256){
    int s = w, c = lane;
    float Lv[7];
    for (int jj=0; jj<7; jj++){
      int j = (s+1+jj)&7;
      float d  = sPB[s][c]-sPB[j][c];
      float dn = sPD[s][c]+sPD[j][c];
      float part = d*d/dn + logf(dn);
      float tot = wsum32(part);
      if (c==0){
        float sim = -0.5f*(tot/32.0f);
        Lv[jj] = (scntV[j]>0) ? sim*2.0f : NEG_INF;   // /TEMP
      }
    }
    if (c==0){
      float Lmax = NEG_INF;
      #pragma unroll
      for (int jj=0;jj<7;jj++) Lmax = fmaxf(Lmax, Lv[jj]);
      #pragma unroll
      for (int jj=0;jj<7;jj++){
        float a = -(Lv[jj]-Lmax);
        if (!(a < 80.0f)) a = 80.0f;
        g_w7[s*7+jj] = expf(a);
      }
    }
  }
}

// ---------------- K3b: stable rank tables via match_any, 8 warps/chunk ----------------
__global__ void k3b_rank(){
  __shared__ int scV[8][8], scH[8][8];
  __shared__ int runV[8][8], runH[8][8];
  int chunk = blockIdx.x;
  int t = threadIdx.x, w = t>>5, lane = t&31;
  unsigned lt = (1u<<lane)-1u;
  if (lane < 8){ scV[w][lane] = 0; scH[w][lane] = 0; }
  uint8_t byt[4];
  #pragma unroll
  for (int g=0; g<4; g++){
    int n = chunk*CHUNK + w*128 + g*32 + lane;
    byt[g] = g_cls[n];
    bool val = (byt[g] != 0xFF);
    int cls = byt[g] & 7;
    int key = val ? cls : (256 + lane);
    unsigned mV = __match_any_sync(0xFFFFFFFFu, key);
    unsigned mH = mV & __ballot_sync(0xFFFFFFFFu, val && (byt[g] & 16));
    if (val){
      int leader = __ffs(mV) - 1;
      if (lane == leader){
        scV[w][cls] += __popc(mV);
        scH[w][cls] += __popc(mH);
      }
    }
    __syncwarp();
  }
  __syncthreads();
  if (lane < 8){
    int bv = g_offV[lane*NCHUNK+chunk], bh = g_offH[lane*NCHUNK+chunk];
    for (int ww=0; ww<w; ww++){ bv += scV[ww][lane]; bh += scH[ww][lane]; }
    runV[w][lane] = bv; runH[w][lane] = bh;
  }
  __syncwarp();
  #pragma unroll
  for (int g=0; g<4; g++){
    int n = chunk*CHUNK + w*128 + g*32 + lane;
    bool val = (byt[g] != 0xFF);
    int cls = byt[g] & 7;
    bool hrd = val && (byt[g] & 16);
    int key = val ? cls : (256 + lane);
    unsigned mV = __match_any_sync(0xFFFFFFFFu, key);
    unsigned mH = mV & __ballot_sync(0xFFFFFFFFu, hrd);
    int leader = __ffs(mV) - 1;
    int baseV = 0, baseH = 0;
    if (val && lane == leader){
      baseV = runV[w][cls]; runV[w][cls] = baseV + __popc(mV);
      baseH = runH[w][cls]; runH[w][cls] = baseH + __popc(mH);
    }
    __syncwarp();
    baseV = __shfl_sync(0xFFFFFFFFu, baseV, leader);
    baseH = __shfl_sync(0xFFFFFFFFu, baseH, leader);
    if (val){
      g_tblV[cls*TBLSTRIDE + baseV + __popc(mV & lt)] = n;
      if (hrd) g_tblH[cls*TBLSTRIDE + baseH + __popc(mH & lt)] = n;
    }
    __syncwarp();
  }
}

// ---------------- K567: anchor + negatives + MLS logits + logsumexp (fused) ----------------
__global__ void k567_mls(){
  __shared__ float sA[32], sD[32], sl[257], w7s[7], sred[8], sM;
  __shared__ int snp[256], scnt8[8], sapix;
  __shared__ uint32_t skey[4];
  int iq = blockIdx.x; int i = iq>>8, q = iq&255; int t = threadIdx.x;
  if (t < 8) scnt8[t] = g_countV[t];
  if (t < 7) w7s[t] = g_w7[i*7+t];
  if (t == 0){
    uint2 keyi = tf2(0u, 42u, 0u, (uint32_t)i);
    uint2 ka   = tf2(keyi.x, keyi.y, 0u, 0u);
    uint2 kb   = tf2(keyi.x, keyi.y, 0u, 1u);
    uint2 kc   = tf2(keyi.x, keyi.y, 0u, 2u);
    skey[0]=kb.x; skey[1]=kb.y; skey[2]=kc.x; skey[3]=kc.y;
    uint2 bu   = tf2(ka.x, ka.y, 0u, (uint32_t)q);
    float u = u01f(bu.x ^ bu.y);
    int hc = g_countH[i];
    int r = (int)(u * (float)hc);
    int rm = hc - 1; if (rm < 0) rm = 0;
    if (r > rm) r = rm;
    sapix = g_tblH[i*TBLSTRIDE + r];
  }
  __syncthreads();
  if (t < 32){
    float2 v = g_BD[(size_t)sapix*CC + t];
    sA[t] = v.x; sD[t] = v.y;
  }
  // per-thread negative sampling (exact threefry layout: uniform (Q,NEG,7))
  uint32_t kbx = skey[0], kby = skey[1];
  uint32_t base = ((uint32_t)q*256u + (uint32_t)t)*7u;
  int best = 0; float bs = POS_INF;
  #pragma unroll
  for (int jj=0; jj<7; jj++){
    uint2 bb = tf2(kbx, kby, 0u, base + (uint32_t)jj);
    float u = u01f(bb.x ^ bb.y);
    float f = fmaxf(u + TINYF, TINYF);
    float score = (-__logf(f)) * w7s[jj];   // argmin == argmax(gumbel+logit)
    if (score < bs){ bs = score; best = jj; }
  }
  int nc  = (i + 1 + best) & 7;
  int cntc = scnt8[nc];
  uint2 b3 = tf2(skey[2], skey[3], 0u, (uint32_t)(q*256 + t));
  float u3 = u01f(b3.x ^ b3.y);
  int r = (int)(u3 * (float)cntc);
  int rm = cntc - 1; if (rm < 0) rm = 0;
  if (r > rm) r = rm;
  snp[t] = g_tblV[nc*TBLSTRIDE + r];
  __syncthreads();
  // MLS logits: 2 rows per warp iteration (MLP=2), lane = channel, float2 gathers
  int w = t>>5, c = t&31;
  float A = sA[c], Da = sD[c];
  for (int j = w; j < 257; j += 16){
    int j2 = j + 8;
    bool h2 = (j2 < 257);
    float2 bd1, bd2 = make_float2(0.f, 1.f);
    if (j == 0){ bd1 = make_float2(g_posB[i*CC+c], g_posD[i*CC+c]); }
    else { bd1 = g_BD[(size_t)snp[j-1]*CC + c]; }
    if (h2){ bd2 = g_BD[(size_t)snp[j2-1]*CC + c]; }
    float dn1 = Da + bd1.y, d1 = A - bd1.x;
    float p1 = __fdividef(d1*d1, dn1) + __logf(dn1);
    float dn2 = Da + bd2.y, d2 = A - bd2.x;
    float p2 = __fdividef(d2*d2, dn2) + __logf(dn2);
    float t1 = wsum32(p1);
    float t2 = wsum32(p2);
    if (c == 0){
      sl[j] = -t1*(1.0f/32.0f);             // -0.5*mean/TEMP
      if (h2) sl[j2] = -t2*(1.0f/32.0f);
    }
  }
  __syncthreads();
  // logsumexp: warp-shuffle two-level reduction
  float v = sl[t]; if (t == 0) v = fmaxf(v, sl[256]);
  float m = wmax32(v);
  if (c == 0) sred[w] = m;
  __syncthreads();
  if (t == 0){
    float M = sred[0];
    #pragma unroll
    for (int k = 1; k < 8; k++) M = fmaxf(M, sred[k]);
    sM = M;
  }
  __syncthreads();
  float M = sM;
  float e = __expf(v - M); if (t == 0) e += __expf(sl[256] - M);
  float s = wsum32(e);
  if (c == 0) sred[w] = s;
  __syncthreads();
  if (t == 0){
    float S = 0.0f;
    #pragma unroll
    for (int k = 0; k < 8; k++) S += sred[k];
    g_ce[iq] = (logf(S) + M) - sl[0];
  }
}

// ---------------- K8: parallel final reduction + restore proto zeros ----------------
__global__ void k8_final(float* out){
  __shared__ float cls[8];
  int t = threadIdx.x, w = t>>5, lane = t&31;
  float s = 0.0f;
  #pragma unroll
  for (int k = 0; k < 8; k++) s += g_ce[w*QQ + k*32 + lane];
  s = wsum32(s);
  if (lane == 0) cls[w] = s * (1.0f/(float)QQ);
  // re-zero proto accumulators for the next call (invariant: zero at entry)
  for (int i = t; i < SS*CC*3; i += 256) g_protoLL[i] = 0ull;
  __syncthreads();
  if (t == 0){
    int vn = 0; float tot = 0.0f;
    for (int i = 0; i < SS; i++) if (g_countV[i] > 0) vn++;
    for (int i = 0; i < SS; i++)
      if (g_countV[i] > 0 && g_countH[i] > 0) tot += cls[i];
    out[0] = tot / (float)(vn > 0 ? vn : 1);
  }
}

extern "C" void kernel_launch(void* const* d_in, const int* in_sizes, int n_in,
                              void* d_out, int out_size){
  const float* W  = (const float*)d_in[0];
  const float* MU = (const float*)d_in[1];
  const float* SG = (const float*)d_in[2];
  const float* LB = (const float*)d_in[3];
  const float* MK = (const float*)d_in[4];
  const float* PR = (const float*)d_in[5];
  float* out = (float*)d_out;
  k1_classify<<<NCHUNK,256>>>(LB, MK, PR);
  k2_transpose<<<NN/64,256>>>(W, MU, SG);
  k34_scan_proto<<<1,512>>>();
  k3b_rank<<<NCHUNK,256>>>();
  k567_mls<<<SS*QQ,256>>>();
  k8_final<<<1,256>>>(out);
}